// round 14
// baseline (speedup 1.0000x reference)
#include <cuda_runtime.h>
#include <cuda_fp16.h>
#include <math.h>
#include <stdint.h>

#define BATCH      2048
#define NODES      12
#define NTOK       (BATCH * NODES)     // 24576
#define D          128
#define F          512
#define NHEAD      4
#define DH         32
#define SCALE      0.17677669529663687f

typedef __half fp16;

// ---------------- scratch (device globals; no allocation) ----------------
__device__ __align__(16) float g_x   [NTOK * D];
__device__ __align__(16) fp16 g_qkv [NTOK * 384];
__device__ __align__(16) fp16 g_h [NTOK * D];
__device__ __align__(16) fp16 g_m [NTOK * D];
__device__ __align__(16) fp16 g_t [NTOK * F];
__device__ __align__(16) fp16 g_wqkv[2 * 384 * D];   // [l][n][k]
__device__ __align__(16) fp16 g_wo  [2 * D * D];
__device__ __align__(16) fp16 g_w1  [2 * F * D];
__device__ __align__(16) fp16 g_w2  [2 * D * F];
__device__ float g_bqkv[2 * 384];

__device__ __forceinline__ float gelu_exact(float x) {
    return 0.5f * x * (1.0f + erff(x * 0.7071067811865476f));
}
__device__ __forceinline__ uint32_t smem_u32(const void* p) {
    uint32_t a;
    asm("{ .reg .u64 t; cvta.to.shared.u64 t, %1; cvt.u32.u64 %0, t; }" : "=r"(a) : "l"(p));
    return a;
}
__device__ __forceinline__ void cp16(uint32_t dst, const void* src) {
    asm volatile("cp.async.ca.shared.global [%0], [%1], 16;" :: "r"(dst), "l"(src));
}
#define CP_COMMIT() asm volatile("cp.async.commit_group;" ::: "memory")
#define CP_WAIT(n)  asm volatile("cp.async.wait_group %0;" :: "n"(n) : "memory")

__device__ __forceinline__ void ldsm4(uint32_t* r, uint32_t addr) {
    asm volatile("ldmatrix.sync.aligned.m8n8.x4.shared.b16 {%0,%1,%2,%3}, [%4];"
        : "=r"(r[0]), "=r"(r[1]), "=r"(r[2]), "=r"(r[3]) : "r"(addr));
}
__device__ __forceinline__ void mma_f16(float* c, const uint32_t* a, uint32_t b0, uint32_t b1) {
    asm volatile(
        "mma.sync.aligned.m16n8k16.row.col.f32.f16.f16.f32 "
        "{%0,%1,%2,%3}, {%4,%5,%6,%7}, {%8,%9}, {%0,%1,%2,%3};"
        : "+f"(c[0]), "+f"(c[1]), "+f"(c[2]), "+f"(c[3])
        : "r"(a[0]), "r"(a[1]), "r"(a[2]), "r"(a[3]), "r"(b0), "r"(b1));
}

// ---------------- init + layer0 LN1 ----------------
__global__ void init_ln_kernel(const float* __restrict__ patch,
                               const float* __restrict__ band,
                               const float* __restrict__ summ,
                               const float* __restrict__ s, const float* __restrict__ b,
                               float* __restrict__ x, fp16* __restrict__ oh) {
    int row  = blockIdx.x * 4 + (threadIdx.x >> 5);
    int lane = threadIdx.x & 31;
    int node = row % NODES;
    int bb   = row / NODES;
    float v[4];
    float sum = 0.f;
#pragma unroll
    for (int i = 0; i < 4; i++) {
        int d = lane + 32 * i;
        float val;
        if (node < 6)       val = patch[(size_t)(bb * 6 + node) * D + d];
        else if (node < 11) val = band [(size_t)(bb * 5 + (node - 6)) * D + d];
        else                val = summ[d];
        v[i] = val;
        x[(size_t)row * D + d] = val;
        sum += val;
    }
#pragma unroll
    for (int o = 16; o; o >>= 1) sum += __shfl_xor_sync(0xffffffffu, sum, o);
    float mu = sum * (1.0f / 128.0f);
    float sq = 0.f;
#pragma unroll
    for (int i = 0; i < 4; i++) { float c = v[i] - mu; sq += c * c; }
#pragma unroll
    for (int o = 16; o; o >>= 1) sq += __shfl_xor_sync(0xffffffffu, sq, o);
    float inv = rsqrtf(sq * (1.0f / 128.0f) + 1e-5f);
#pragma unroll
    for (int i = 0; i < 4; i++) {
        int d = lane + 32 * i;
        float y = (v[i] - mu) * inv * s[d] + b[d];
        oh[(size_t)row * D + d] = __float2half_rn(y);
    }
}

// ---------------- weight packing (single fp16, [n][k] layout) ----------------
__global__ void pack_qkvw_kernel(const float* __restrict__ wq, const float* __restrict__ wk,
                                 const float* __restrict__ wv,
                                 const float* __restrict__ bq, const float* __restrict__ bk,
                                 const float* __restrict__ bv,
                                 fp16* __restrict__ qw, float* __restrict__ bqkv) {
    int idx = blockIdx.x * 256 + threadIdx.x;
    if (idx < 98304) {
        int l = idx / 49152, r = idx % 49152;
        int n = r / 128, k = r % 128;
        const float* src = (n < 128) ? wq : ((n < 256) ? wk : wv);
        qw[idx] = __float2half_rn(src[(size_t)l * 16384 + k * 128 + (n & 127)]);
    }
    if (idx < 768) {
        int l = idx / 384, n = idx % 384;
        const float* sb = (n < 128) ? bq : ((n < 256) ? bk : bv);
        bqkv[idx] = sb[l * 128 + (n & 127)];
    }
}
__global__ void pack_rest_kernel(const float* __restrict__ wo,
                                 const float* __restrict__ w1, const float* __restrict__ w2,
                                 fp16* __restrict__ ow, fp16* __restrict__ w1w,
                                 fp16* __restrict__ w2w) {
    int idx = blockIdx.x * 256 + threadIdx.x;
    if (idx < 32768) {
        int l = idx / 16384, r = idx % 16384;
        int n = r / 128, k = r % 128;
        ow[idx] = __float2half_rn(wo[(size_t)l * 16384 + k * 128 + n]);
    } else if (idx < 163840) {
        int t = idx - 32768;
        int l = t / 65536, r = t % 65536;
        int n = r / 128, k = r % 128;
        w1w[t] = __float2half_rn(w1[(size_t)l * 65536 + (size_t)k * 512 + n]);
    } else if (idx < 294912) {
        int t = idx - 163840;
        int l = t / 65536, r = t % 65536;
        int n = r / 512, k = r % 512;
        w2w[t] = __float2half_rn(w2[(size_t)l * 65536 + (size_t)k * 128 + n]);
    }
}

// ---------------- fp16 GEMM (big): BM=128 BN=128 BK=32, 256 thr, 2 CTAs/SM ------------
// All 12 LDSM of a stage hoisted before the MMA block (load-use distance maximized).
// mode 0: oh = half(D + bias);  mode 2: oh = half(gelu(D+bias))
#define STG_B   24576
#define GEMM_SMEM 73728

__global__ __launch_bounds__(256, 2) void tgemm_kernel(
    const fp16* __restrict__ A, const fp16* __restrict__ W, int K,
    const float* __restrict__ bias,
    fp16* __restrict__ oh, int ldh, int mode) {
    extern __shared__ __align__(16) char sm[];
    uint32_t sb = smem_u32(sm);
    const int tid = threadIdx.x, lane = tid & 31, wid = tid >> 5;
    const int bm = blockIdx.y * 128, bn = blockIdx.x * 128;
    const int wm = (wid & 3) * 32, wn = (wid >> 2) * 64;
    const int nst = K >> 5;

    const int lrow = tid >> 1, lhf = tid & 1;
    const fp16* p0 = A + (size_t)(bm + lrow) * K + lhf * 8;
    const fp16* p1 = W + (size_t)(bn + lrow) * K + lhf * 8;
    const uint32_t d0 = (uint32_t)(lrow * 48 + lhf * 16);

    float acc[2][8][4];
#pragma unroll
    for (int i = 0; i < 2; i++)
#pragma unroll
        for (int j = 0; j < 8; j++)
#pragma unroll
            for (int c = 0; c < 4; c++) acc[i][j][c] = 0.f;

    const uint32_t aoff = (uint32_t)((lane & 15) * 48 + (lane >> 4) * 16);
    const uint32_t boff = (uint32_t)(((((lane >> 4) << 3) + (lane & 7)) * 48) + ((lane >> 3) & 1) * 16);

#define LOAD_STAGE(s) do { \
    uint32_t base_ = sb + ((s) % 3) * STG_B; \
    int ko_ = (s) * 32; \
    cp16(base_ + d0,          p0 + ko_); \
    cp16(base_ + 6144 + d0,   p0 + ko_ + 16); \
    cp16(base_ + 12288 + d0,  p1 + ko_); \
    cp16(base_ + 18432 + d0,  p1 + ko_ + 16); \
} while (0)

    LOAD_STAGE(0); CP_COMMIT();
    if (nst > 1) { LOAD_STAGE(1); CP_COMMIT(); }

    for (int s = 0; s < nst; s++) {
        if (s + 1 < nst) CP_WAIT(1); else CP_WAIT(0);
        __syncthreads();
        if (s + 2 < nst) { LOAD_STAGE(s + 2); CP_COMMIT(); }

        uint32_t base = sb + (s % 3) * STG_B;
        uint32_t fa[2][2][4], fw[2][4][4];
#pragma unroll
        for (int mi = 0; mi < 2; mi++) {
            uint32_t ad = base + (uint32_t)((wm + mi * 16) * 48) + aoff;
            ldsm4(fa[0][mi], ad);
            ldsm4(fa[1][mi], ad + 6144);
        }
#pragma unroll
        for (int sub = 0; sub < 2; sub++)
#pragma unroll
            for (int nj = 0; nj < 4; nj++)
                ldsm4(fw[sub][nj],
                      base + 12288u + (uint32_t)sub * 6144u + (uint32_t)((wn + nj * 16) * 48) + boff);
#pragma unroll
        for (int sub = 0; sub < 2; sub++)
#pragma unroll
            for (int nj = 0; nj < 4; nj++)
#pragma unroll
                for (int mi = 0; mi < 2; mi++) {
                    mma_f16(acc[mi][nj * 2],     fa[sub][mi], fw[sub][nj][0], fw[sub][nj][1]);
                    mma_f16(acc[mi][nj * 2 + 1], fa[sub][mi], fw[sub][nj][2], fw[sub][nj][3]);
                }
    }

#pragma unroll
    for (int mi = 0; mi < 2; mi++) {
        int r0 = bm + wm + mi * 16 + (lane >> 2);
        int r1 = r0 + 8;
#pragma unroll
        for (int ni = 0; ni < 8; ni++) {
            int col = bn + wn + ni * 8 + 2 * (lane & 3);
            float b0 = bias[col], b1 = bias[col + 1];
            float v0 = acc[mi][ni][0] + b0, v1 = acc[mi][ni][1] + b1;
            float v2 = acc[mi][ni][2] + b0, v3 = acc[mi][ni][3] + b1;
            size_t o0 = (size_t)r0 * ldh + col, o1 = (size_t)r1 * ldh + col;
            if (mode == 2) {
                v0 = gelu_exact(v0); v1 = gelu_exact(v1);
                v2 = gelu_exact(v2); v3 = gelu_exact(v3);
            }
            __half2 h0 = __floats2half2_rn(v0, v1);
            __half2 h1 = __floats2half2_rn(v2, v3);
            *(__half2*)&oh[o0] = h0;
            *(__half2*)&oh[o1] = h1;
        }
    }
#undef LOAD_STAGE
}

// ---------------- fp16 GEMM (small-M): BM=64 BN=128 BK=32, 256 thr, 3 CTAs/SM --------
#define STG64_B  18432
#define GEMM64_SMEM 55296

__global__ __launch_bounds__(256, 3) void tgemm64_kernel(
    const fp16* __restrict__ A, const fp16* __restrict__ W, int K,
    const float* __restrict__ bias,
    float* __restrict__ outf,
    fp16* __restrict__ oh,
    const float* __restrict__ resid,
    const float* __restrict__ ln_s, const float* __restrict__ ln_b) {
    extern __shared__ __align__(16) char sm[];
    uint32_t sb = smem_u32(sm);
    const int tid = threadIdx.x, lane = tid & 31, wid = tid >> 5;
    const int bm = blockIdx.y * 64;
    const int wm = (wid & 1) * 32, wn = (wid >> 1) * 32;
    const int nst = K >> 5;

    const int asub = tid >> 7, at = tid & 127;
    const int arow = at >> 1, ahf = at & 1;
    const fp16* pa = A + (size_t)(bm + arow) * K + asub * 16 + ahf * 8;
    const uint32_t da = (uint32_t)(asub * 3072 + arow * 48 + ahf * 16);
    const int wrow = tid >> 1, whf = tid & 1;
    const fp16* pw = W + (size_t)wrow * K + whf * 8;
    const uint32_t dw = (uint32_t)(6144 + wrow * 48 + whf * 16);

    float acc[2][4][4];
#pragma unroll
    for (int i = 0; i < 2; i++)
#pragma unroll
        for (int j = 0; j < 4; j++)
#pragma unroll
            for (int c = 0; c < 4; c++) acc[i][j][c] = 0.f;

    const uint32_t aoff = (uint32_t)((lane & 15) * 48 + (lane >> 4) * 16);
    const uint32_t boff = (uint32_t)(((((lane >> 4) << 3) + (lane & 7)) * 48) + ((lane >> 3) & 1) * 16);

#define LOAD_STAGE64(s) do { \
    uint32_t base_ = sb + ((s) % 3) * STG64_B; \
    int ko_ = (s) * 32; \
    cp16(base_ + da,         pa + ko_); \
    cp16(base_ + dw,         pw + ko_); \
    cp16(base_ + 6144 + dw,  pw + ko_ + 16); \
} while (0)

    LOAD_STAGE64(0); CP_COMMIT();
    if (nst > 1) { LOAD_STAGE64(1); CP_COMMIT(); }

    for (int s = 0; s < nst; s++) {
        if (s + 1 < nst) CP_WAIT(1); else CP_WAIT(0);
        __syncthreads();
        if (s + 2 < nst) { LOAD_STAGE64(s + 2); CP_COMMIT(); }

        uint32_t base = sb + (s % 3) * STG64_B;
#pragma unroll
        for (int sub = 0; sub < 2; sub++) {
            uint32_t fa[2][4];
#pragma unroll
            for (int mi = 0; mi < 2; mi++)
                ldsm4(fa[mi], base + (uint32_t)sub * 3072u + (uint32_t)((wm + mi * 16) * 48) + aoff);
            uint32_t wb = base + 6144u + (uint32_t)sub * 6144u;
#pragma unroll
            for (int nj = 0; nj < 2; nj++) {
                uint32_t fw[4];
                ldsm4(fw, wb + (uint32_t)((wn + nj * 16) * 48) + boff);
#pragma unroll
                for (int mi = 0; mi < 2; mi++) {
                    mma_f16(acc[mi][nj * 2],     fa[mi], fw[0], fw[1]);
                    mma_f16(acc[mi][nj * 2 + 1], fa[mi], fw[2], fw[3]);
                }
            }
        }
    }
    __syncthreads();

    float* smf = (float*)sm;  // 64x128 f32 = 32KB
#pragma unroll
    for (int mi = 0; mi < 2; mi++) {
        int lr0 = wm + mi * 16 + (lane >> 2);
        int lr1 = lr0 + 8;
#pragma unroll
        for (int ni = 0; ni < 4; ni++) {
            int col = wn + ni * 8 + 2 * (lane & 3);
            float b0 = bias[col], b1 = bias[col + 1];
            size_t o0 = (size_t)(bm + lr0) * 128 + col, o1 = (size_t)(bm + lr1) * 128 + col;
            float v0 = acc[mi][ni][0] + b0 + resid[o0];
            float v1 = acc[mi][ni][1] + b1 + resid[o0 + 1];
            float v2 = acc[mi][ni][2] + b0 + resid[o1];
            float v3 = acc[mi][ni][3] + b1 + resid[o1 + 1];
            *(float2*)&outf[o0] = make_float2(v0, v1);
            *(float2*)&outf[o1] = make_float2(v2, v3);
            smf[lr0 * 128 + col] = v0; smf[lr0 * 128 + col + 1] = v1;
            smf[lr1 * 128 + col] = v2; smf[lr1 * 128 + col + 1] = v3;
        }
    }
    if (ln_s) {
        __syncthreads();
        float4 s4 = *(const float4*)(ln_s + lane * 4);
        float4 b4 = *(const float4*)(ln_b + lane * 4);
#pragma unroll
        for (int t = 0; t < 8; t++) {
            int rr = wid * 8 + t;
            float4 v = ((const float4*)smf)[rr * 32 + lane];
            float sum = (v.x + v.y) + (v.z + v.w);
            float sq  = fmaf(v.x, v.x, fmaf(v.y, v.y, fmaf(v.z, v.z, v.w * v.w)));
#pragma unroll
            for (int o = 16; o; o >>= 1) {
                sum += __shfl_xor_sync(0xffffffffu, sum, o);
                sq  += __shfl_xor_sync(0xffffffffu, sq, o);
            }
            float mu  = sum * (1.0f / 128.0f);
            float var = sq * (1.0f / 128.0f) - mu * mu;
            float inv = rsqrtf(var + 1e-5f);
            __half2 h0 = __floats2half2_rn((v.x - mu) * inv * s4.x + b4.x,
                                           (v.y - mu) * inv * s4.y + b4.y);
            __half2 h1 = __floats2half2_rn((v.z - mu) * inv * s4.z + b4.z,
                                           (v.w - mu) * inv * s4.w + b4.w);
            uint2 uh{*(uint32_t*)&h0, *(uint32_t*)&h1};
            *(uint2*)(oh + (size_t)(bm + rr) * 128 + lane * 4) = uh;
        }
    }
#undef LOAD_STAGE64
}

// ---------------- attention: 4 batches per 192-thread CTA ----------------
#define ATTN_SMEM (2 * 4 * NODES * D * 4 + 144)
__global__ __launch_bounds__(192) void attn_kernel(const fp16* __restrict__ qkv,
                                                   const float* __restrict__ edge_bias,
                                                   fp16* __restrict__ mh) {
    extern __shared__ __align__(16) float asm_[];
    float* sk = asm_;                     // [4*12*128]
    float* sv = asm_ + 4 * NODES * D;     // [4*12*128]
    float* seb = sv + 4 * NODES * D;      // [36]
    int b0 = blockIdx.x * 4;
    const uint4* src = (const uint4*)(qkv + (size_t)b0 * NODES * 384);
    for (int i = threadIdx.x; i < 4 * NODES * 32; i += 192) {
        int lbn = i >> 5;                 // lb*12 + node
        int c = i & 31;
        uint4 u = src[lbn * 48 + 16 + c];
        float* dp = (c < 16) ? &sk[lbn * D + c * 8] : &sv[lbn * D + (c - 16) * 8];
        float2 f0 = __half22float2(*(__half2*)&u.x);
        float2 f1 = __half22float2(*(__half2*)&u.y);
        float2 f2 = __half22float2(*(__half2*)&u.z);
        float2 f3 = __half22float2(*(__half2*)&u.w);
        dp[0] = f0.x; dp[1] = f0.y; dp[2] = f1.x; dp[3] = f1.y;
        dp[4] = f2.x; dp[5] = f2.y; dp[6] = f3.x; dp[7] = f3.y;
    }
    if (threadIdx.x < 36) seb[threadIdx.x] = edge_bias[threadIdx.x];
    __syncthreads();

    int lb = threadIdx.x / 48;
    int t  = threadIdx.x % 48;
    int dst = t >> 2, hd = t & 3;
    int kd = dst < 6 ? 0 : (dst < 11 ? 1 : 2);
    int lbase = lb * NODES;

    float q[DH];
    {
        const uint4* qp = src + (lbase + dst) * 48 + hd * 4;
#pragma unroll
        for (int i = 0; i < 4; i++) {
            uint4 u = qp[i];
            float2 f0 = __half22float2(*(__half2*)&u.x);
            float2 f1 = __half22float2(*(__half2*)&u.y);
            float2 f2 = __half22float2(*(__half2*)&u.z);
            float2 f3 = __half22float2(*(__half2*)&u.w);
            q[i * 8 + 0] = f0.x; q[i * 8 + 1] = f0.y; q[i * 8 + 2] = f1.x; q[i * 8 + 3] = f1.y;
            q[i * 8 + 4] = f2.x; q[i * 8 + 5] = f2.y; q[i * 8 + 6] = f3.x; q[i * 8 + 7] = f3.y;
        }
    }

    float logits[NODES];
    float mx = -1e30f;
#pragma unroll
    for (int j = 0; j < NODES; j++) {
        const float4* kp = (const float4*)&sk[(lbase + j) * D + hd * DH];
        float d0 = 0.f, d1 = 0.f, d2 = 0.f, d3 = 0.f;
#pragma unroll
        for (int i = 0; i < 8; i++) {
            float4 kv = kp[i];
            d0 = fmaf(q[i * 4 + 0], kv.x, d0);
            d1 = fmaf(q[i * 4 + 1], kv.y, d1);
            d2 = fmaf(q[i * 4 + 2], kv.z, d2);
            d3 = fmaf(q[i * 4 + 3], kv.w, d3);
        }
        int ks = j < 6 ? 0 : (j < 11 ? 1 : 2);
        float lg = ((d0 + d1) + (d2 + d3)) * SCALE + seb[(ks * 3 + kd) * NHEAD + hd];
        logits[j] = lg;
        mx = fmaxf(mx, lg);
    }
    float z = 0.f;
#pragma unroll
    for (int j = 0; j < NODES; j++) { logits[j] = __expf(logits[j] - mx); z += logits[j]; }
    float inv = 1.0f / z;

    float4 out[8];
#pragma unroll
    for (int i = 0; i < 8; i++) out[i] = make_float4(0.f, 0.f, 0.f, 0.f);
#pragma unroll
    for (int j = 0; j < NODES; j++) {
        float a = logits[j] * inv;
        const float4* vp = (const float4*)&sv[(lbase + j) * D + hd * DH];
#pragma unroll
        for (int i = 0; i < 8; i++) {
            float4 vv = vp[i];
            out[i].x = fmaf(a, vv.x, out[i].x);
            out[i].y = fmaf(a, vv.y, out[i].y);
            out[i].z = fmaf(a, vv.z, out[i].z);
            out[i].w = fmaf(a, vv.w, out[i].w);
        }
    }
    size_t ob = (size_t)(b0 + lb) * NODES * D + dst * D + hd * DH;
#pragma unroll
    for (int i = 0; i < 8; i++) {
        __half2 h0 = __floats2half2_rn(out[i].x, out[i].y);
        __half2 h1 = __floats2half2_rn(out[i].z, out[i].w);
        uint2 uh{*(uint32_t*)&h0, *(uint32_t*)&h1};
        *(uint2*)(mh + ob + i * 4) = uh;
    }
}

// ---------------- final: gate/pool + proj + LN + gelu ----------------
__global__ void final_kernel(const float* __restrict__ x,
                             const float* __restrict__ gate_w, const float* __restrict__ gate_b,
                             const float* __restrict__ proj_w, const float* __restrict__ proj_b,
                             const float* __restrict__ pln_s, const float* __restrict__ pln_b,
                             float* __restrict__ out) {
    __shared__ float sx[NODES * D];
    __shared__ float sgate[NODES];
    __shared__ float comb[2 * D];
    __shared__ float red[4];
    int b = blockIdx.x, tid = threadIdx.x;
    for (int i = tid; i < NODES * D; i += 128) sx[i] = x[(size_t)b * NODES * D + i];
    __syncthreads();
    if (tid < NODES) {
        float acc = gate_b[0];
#pragma unroll 8
        for (int d = 0; d < D; d++) acc = fmaf(sx[tid * D + d], gate_w[d], acc);
        sgate[tid] = 1.0f / (1.0f + __expf(-acc));
    }
    __syncthreads();
    float pooled = 0.f;
#pragma unroll
    for (int n = 0; n < NODES; n++) pooled = fmaf(sx[n * D + tid], sgate[n], pooled);
    comb[tid]     = sx[11 * D + tid];
    comb[D + tid] = pooled;
    __syncthreads();
    float y = proj_b[tid];
#pragma unroll 8
    for (int c = 0; c < 2 * D; c++) y = fmaf(comb[c], proj_w[c * D + tid], y);
    float sum = y;
#pragma unroll
    for (int o = 16; o; o >>= 1) sum += __shfl_xor_sync(0xffffffffu, sum, o);
    if ((tid & 31) == 0) red[tid >> 5] = sum;
    __syncthreads();
    float mu = (red[0] + red[1] + red[2] + red[3]) * (1.0f / 128.0f);
    float c0 = y - mu;
    float cs = c0 * c0;
#pragma unroll
    for (int o = 16; o; o >>= 1) cs += __shfl_xor_sync(0xffffffffu, cs, o);
    __syncthreads();
    if ((tid & 31) == 0) red[tid >> 5] = cs;
    __syncthreads();
    float var = (red[0] + red[1] + red[2] + red[3]) * (1.0f / 128.0f);
    float yn = c0 * rsqrtf(var + 1e-5f) * pln_s[tid] + pln_b[tid];
    out[(size_t)b * D + tid] = gelu_exact(yn);
}

// ---------------- host orchestration ----------------
extern "C" void kernel_launch(void* const* d_in, const int* in_sizes, int n_in,
                              void* d_out, int out_size) {
    const float* patch   = (const float*)d_in[0];
    const float* band    = (const float*)d_in[1];
    const float* summ    = (const float*)d_in[2];
    const float* ln1_s   = (const float*)d_in[3];
    const float* ln1_b   = (const float*)d_in[4];
    const float* wq      = (const float*)d_in[5];
    const float* bq      = (const float*)d_in[6];
    const float* wk      = (const float*)d_in[7];
    const float* bk      = (const float*)d_in[8];
    const float* wv      = (const float*)d_in[9];
    const float* bv      = (const float*)d_in[10];
    const float* wo      = (const float*)d_in[11];
    const float* bo      = (const float*)d_in[12];
    const float* edge_b  = (const float*)d_in[13];
    const float* ln2_s   = (const float*)d_in[14];
    const float* ln2_b   = (const float*)d_in[15];
    const float* w1      = (const float*)d_in[16];
    const float* b1      = (const float*)d_in[17];
    const float* w2      = (const float*)d_in[18];
    const float* b2      = (const float*)d_in[19];
    const float* gate_w  = (const float*)d_in[20];
    const float* gate_b  = (const float*)d_in[21];
    const float* proj_w  = (const float*)d_in[22];
    const float* proj_b  = (const float*)d_in[23];
    const float* pln_s   = (const float*)d_in[24];
    const float* pln_b   = (const float*)d_in[25];
    float* out = (float*)d_out;

    float *x, *bqkv;
    fp16 *qkv, *hbuf, *mbuf, *tbuf;
    fp16 *wqkvw, *wow, *w1w, *w2w;
    cudaGetSymbolAddress((void**)&x,     g_x);
    cudaGetSymbolAddress((void**)&qkv,   g_qkv);
    cudaGetSymbolAddress((void**)&bqkv,  g_bqkv);
    cudaGetSymbolAddress((void**)&hbuf,  g_h);
    cudaGetSymbolAddress((void**)&mbuf,  g_m);
    cudaGetSymbolAddress((void**)&tbuf,  g_t);
    cudaGetSymbolAddress((void**)&wqkvw, g_wqkv);
    cudaGetSymbolAddress((void**)&wow,   g_wo);
    cudaGetSymbolAddress((void**)&w1w,   g_w1);
    cudaGetSymbolAddress((void**)&w2w,   g_w2);

    static int smem_set = 0;
    if (!smem_set) {
        cudaFuncSetAttribute(tgemm_kernel, cudaFuncAttributeMaxDynamicSharedMemorySize, GEMM_SMEM);
        cudaFuncSetAttribute(tgemm64_kernel, cudaFuncAttributeMaxDynamicSharedMemorySize, GEMM64_SMEM);
        cudaFuncSetAttribute(attn_kernel, cudaFuncAttributeMaxDynamicSharedMemorySize, ATTN_SMEM);
        smem_set = 1;
    }

    init_ln_kernel<<<NTOK / 4, 128>>>(patch, band, summ, ln1_s, ln1_b, x, hbuf);
    pack_qkvw_kernel<<<(98304 + 255) / 256, 256>>>(wq, wk, wv, bq, bk, bv, wqkvw, bqkv);
    pack_rest_kernel<<<(294912 + 255) / 256, 256>>>(wo, w1, w2, wow, w1w, w2w);

    const int MT = NTOK / 128;    // 192
    const int MT64 = NTOK / 64;   // 384
    for (int l = 0; l < 2; l++) {
        tgemm_kernel<<<dim3(3, MT), 256, GEMM_SMEM>>>(
            hbuf, wqkvw + (size_t)l * 384 * 128, 128, bqkv + l * 384, qkv, 384, 0);
        attn_kernel<<<BATCH / 4, 192, ATTN_SMEM>>>(qkv, edge_b + l * 36, mbuf);
        tgemm64_kernel<<<dim3(1, MT64), 256, GEMM64_SMEM>>>(
            mbuf, wow + (size_t)l * 128 * 128, 128,
            bo + l * 128, x, hbuf, x, ln2_s + l * 128, ln2_b + l * 128);
        tgemm_kernel<<<dim3(4, MT), 256, GEMM_SMEM>>>(
            hbuf, w1w + (size_t)l * 512 * 128, 128, b1 + l * 512, tbuf, 512, 2);
        const float* nls = (l == 0) ? (ln1_s + 128) : nullptr;
        const float* nlb = (l == 0) ? (ln1_b + 128) : nullptr;
        tgemm64_kernel<<<dim3(1, MT64), 256, GEMM64_SMEM>>>(
            tbuf, w2w + (size_t)l * 128 * 512, 512,
            b2 + l * 128, x, hbuf, x, nls, nlb);
    }

    final_kernel<<<BATCH, 128>>>(x, gate_w, gate_b, proj_w, proj_b, pln_s, pln_b, out);
}

// round 16
// speedup vs baseline: 1.0398x; 1.0398x over previous
#include <cuda_runtime.h>
#include <cuda_fp16.h>
#include <math.h>
#include <stdint.h>

#define BATCH      2048
#define NODES      12
#define NTOK       (BATCH * NODES)     // 24576
#define D          128
#define F          512
#define NHEAD      4
#define DH         32
#define SCALE      0.17677669529663687f

typedef __half fp16;

// ---------------- scratch (device globals; no allocation) ----------------
__device__ __align__(16) float g_x   [NTOK * D];
__device__ __align__(16) fp16 g_qkv [NTOK * 384];
__device__ __align__(16) fp16 g_h [NTOK * D];
__device__ __align__(16) fp16 g_m [NTOK * D];
__device__ __align__(16) fp16 g_t [NTOK * F];
__device__ __align__(16) fp16 g_wqkv[2 * 384 * D];   // [l][n][k]
__device__ __align__(16) fp16 g_wo  [2 * D * D];
__device__ __align__(16) fp16 g_w1  [2 * F * D];
__device__ __align__(16) fp16 g_w2  [2 * D * F];
__device__ float g_bqkv[2 * 384];

__device__ __forceinline__ float gelu_exact(float x) {
    return 0.5f * x * (1.0f + erff(x * 0.7071067811865476f));
}
__device__ __forceinline__ uint32_t smem_u32(const void* p) {
    uint32_t a;
    asm("{ .reg .u64 t; cvta.to.shared.u64 t, %1; cvt.u32.u64 %0, t; }" : "=r"(a) : "l"(p));
    return a;
}
__device__ __forceinline__ void cp16(uint32_t dst, const void* src) {
    asm volatile("cp.async.cg.shared.global [%0], [%1], 16;" :: "r"(dst), "l"(src));
}
#define CP_COMMIT() asm volatile("cp.async.commit_group;" ::: "memory")
#define CP_WAIT(n)  asm volatile("cp.async.wait_group %0;" :: "n"(n) : "memory")

__device__ __forceinline__ void ldsm4(uint32_t* r, uint32_t addr) {
    asm volatile("ldmatrix.sync.aligned.m8n8.x4.shared.b16 {%0,%1,%2,%3}, [%4];"
        : "=r"(r[0]), "=r"(r[1]), "=r"(r[2]), "=r"(r[3]) : "r"(addr));
}
__device__ __forceinline__ void mma_f16(float* c, const uint32_t* a, uint32_t b0, uint32_t b1) {
    asm volatile(
        "mma.sync.aligned.m16n8k16.row.col.f32.f16.f16.f32 "
        "{%0,%1,%2,%3}, {%4,%5,%6,%7}, {%8,%9}, {%0,%1,%2,%3};"
        : "+f"(c[0]), "+f"(c[1]), "+f"(c[2]), "+f"(c[3])
        : "r"(a[0]), "r"(a[1]), "r"(a[2]), "r"(a[3]), "r"(b0), "r"(b1));
}

// ---------------- init + layer0 LN1 ----------------
__global__ void init_ln_kernel(const float* __restrict__ patch,
                               const float* __restrict__ band,
                               const float* __restrict__ summ,
                               const float* __restrict__ s, const float* __restrict__ b,
                               float* __restrict__ x, fp16* __restrict__ oh) {
    int row  = blockIdx.x * 4 + (threadIdx.x >> 5);
    int lane = threadIdx.x & 31;
    int node = row % NODES;
    int bb   = row / NODES;
    float v[4];
    float sum = 0.f;
#pragma unroll
    for (int i = 0; i < 4; i++) {
        int d = lane + 32 * i;
        float val;
        if (node < 6)       val = patch[(size_t)(bb * 6 + node) * D + d];
        else if (node < 11) val = band [(size_t)(bb * 5 + (node - 6)) * D + d];
        else                val = summ[d];
        v[i] = val;
        x[(size_t)row * D + d] = val;
        sum += val;
    }
#pragma unroll
    for (int o = 16; o; o >>= 1) sum += __shfl_xor_sync(0xffffffffu, sum, o);
    float mu = sum * (1.0f / 128.0f);
    float sq = 0.f;
#pragma unroll
    for (int i = 0; i < 4; i++) { float c = v[i] - mu; sq += c * c; }
#pragma unroll
    for (int o = 16; o; o >>= 1) sq += __shfl_xor_sync(0xffffffffu, sq, o);
    float inv = rsqrtf(sq * (1.0f / 128.0f) + 1e-5f);
#pragma unroll
    for (int i = 0; i < 4; i++) {
        int d = lane + 32 * i;
        float y = (v[i] - mu) * inv * s[d] + b[d];
        oh[(size_t)row * D + d] = __float2half_rn(y);
    }
}

// ---------------- weight packing (single fp16, [n][k] layout) ----------------
__global__ void pack_qkvw_kernel(const float* __restrict__ wq, const float* __restrict__ wk,
                                 const float* __restrict__ wv,
                                 const float* __restrict__ bq, const float* __restrict__ bk,
                                 const float* __restrict__ bv,
                                 fp16* __restrict__ qw, float* __restrict__ bqkv) {
    int idx = blockIdx.x * 256 + threadIdx.x;
    if (idx < 98304) {
        int l = idx / 49152, r = idx % 49152;
        int n = r / 128, k = r % 128;
        const float* src = (n < 128) ? wq : ((n < 256) ? wk : wv);
        qw[idx] = __float2half_rn(src[(size_t)l * 16384 + k * 128 + (n & 127)]);
    }
    if (idx < 768) {
        int l = idx / 384, n = idx % 384;
        const float* sb = (n < 128) ? bq : ((n < 256) ? bk : bv);
        bqkv[idx] = sb[l * 128 + (n & 127)];
    }
}
__global__ void pack_rest_kernel(const float* __restrict__ wo,
                                 const float* __restrict__ w1, const float* __restrict__ w2,
                                 fp16* __restrict__ ow, fp16* __restrict__ w1w,
                                 fp16* __restrict__ w2w) {
    int idx = blockIdx.x * 256 + threadIdx.x;
    if (idx < 32768) {
        int l = idx / 16384, r = idx % 16384;
        int n = r / 128, k = r % 128;
        ow[idx] = __float2half_rn(wo[(size_t)l * 16384 + k * 128 + n]);
    } else if (idx < 163840) {
        int t = idx - 32768;
        int l = t / 65536, r = t % 65536;
        int n = r / 128, k = r % 128;
        w1w[t] = __float2half_rn(w1[(size_t)l * 65536 + (size_t)k * 512 + n]);
    } else if (idx < 294912) {
        int t = idx - 163840;
        int l = t / 65536, r = t % 65536;
        int n = r / 512, k = r % 512;
        w2w[t] = __float2half_rn(w2[(size_t)l * 65536 + (size_t)k * 128 + n]);
    }
}

// ---------------- fp16 GEMM (big): BM=128 BN=128 BK=32, 256 thr, 2 CTAs/SM ------------
// Round-13 inner schedule (fw in nj loop); K compile-time.
// mode 0: oh = half(D + bias);  mode 2: oh = half(gelu(D+bias))
#define STG_B   24576
#define GEMM_SMEM 73728

template<int K>
__global__ __launch_bounds__(256, 2) void tgemm_kernel(
    const fp16* __restrict__ A, const fp16* __restrict__ W,
    const float* __restrict__ bias,
    fp16* __restrict__ oh, int ldh, int mode) {
    extern __shared__ __align__(16) char sm[];
    uint32_t sb = smem_u32(sm);
    const int tid = threadIdx.x, lane = tid & 31, wid = tid >> 5;
    const int bm = blockIdx.y * 128, bn = blockIdx.x * 128;
    const int wm = (wid & 3) * 32, wn = (wid >> 2) * 64;
    constexpr int nst = K >> 5;

    const int lrow = tid >> 1, lhf = tid & 1;
    const fp16* p0 = A + (size_t)(bm + lrow) * K + lhf * 8;
    const fp16* p1 = W + (size_t)(bn + lrow) * K + lhf * 8;
    const uint32_t d0 = (uint32_t)(lrow * 48 + lhf * 16);

    float acc[2][8][4];
#pragma unroll
    for (int i = 0; i < 2; i++)
#pragma unroll
        for (int j = 0; j < 8; j++)
#pragma unroll
            for (int c = 0; c < 4; c++) acc[i][j][c] = 0.f;

    const uint32_t aoff = (uint32_t)((lane & 15) * 48 + (lane >> 4) * 16);
    const uint32_t boff = (uint32_t)(((((lane >> 4) << 3) + (lane & 7)) * 48) + ((lane >> 3) & 1) * 16);

#define LOAD_STAGE(s) do { \
    uint32_t base_ = sb + ((s) % 3) * STG_B; \
    int ko_ = (s) * 32; \
    cp16(base_ + d0,          p0 + ko_); \
    cp16(base_ + 6144 + d0,   p0 + ko_ + 16); \
    cp16(base_ + 12288 + d0,  p1 + ko_); \
    cp16(base_ + 18432 + d0,  p1 + ko_ + 16); \
} while (0)

    LOAD_STAGE(0); CP_COMMIT();
    if (nst > 1) { LOAD_STAGE(1); CP_COMMIT(); }

#pragma unroll
    for (int s = 0; s < nst; s++) {
        if (s + 1 < nst) CP_WAIT(1); else CP_WAIT(0);
        __syncthreads();
        if (s + 2 < nst) { LOAD_STAGE(s + 2); CP_COMMIT(); }

        uint32_t base = sb + (s % 3) * STG_B;
        uint32_t fa[2][2][4];
#pragma unroll
        for (int mi = 0; mi < 2; mi++) {
            uint32_t ad = base + (uint32_t)((wm + mi * 16) * 48) + aoff;
            ldsm4(fa[0][mi], ad);
            ldsm4(fa[1][mi], ad + 6144);
        }
#pragma unroll
        for (int sub = 0; sub < 2; sub++) {
            uint32_t wb = base + 12288u + (uint32_t)sub * 6144u;
#pragma unroll
            for (int nj = 0; nj < 4; nj++) {
                uint32_t fw[4];
                ldsm4(fw, wb + (uint32_t)((wn + nj * 16) * 48) + boff);
#pragma unroll
                for (int mi = 0; mi < 2; mi++) {
                    mma_f16(acc[mi][nj * 2],     fa[sub][mi], fw[0], fw[1]);
                    mma_f16(acc[mi][nj * 2 + 1], fa[sub][mi], fw[2], fw[3]);
                }
            }
        }
    }

#pragma unroll
    for (int mi = 0; mi < 2; mi++) {
        int r0 = bm + wm + mi * 16 + (lane >> 2);
        int r1 = r0 + 8;
#pragma unroll
        for (int ni = 0; ni < 8; ni++) {
            int col = bn + wn + ni * 8 + 2 * (lane & 3);
            float b0 = bias[col], b1 = bias[col + 1];
            float v0 = acc[mi][ni][0] + b0, v1 = acc[mi][ni][1] + b1;
            float v2 = acc[mi][ni][2] + b0, v3 = acc[mi][ni][3] + b1;
            size_t o0 = (size_t)r0 * ldh + col, o1 = (size_t)r1 * ldh + col;
            if (mode == 2) {
                v0 = gelu_exact(v0); v1 = gelu_exact(v1);
                v2 = gelu_exact(v2); v3 = gelu_exact(v3);
            }
            __half2 h0 = __floats2half2_rn(v0, v1);
            __half2 h1 = __floats2half2_rn(v2, v3);
            *(__half2*)&oh[o0] = h0;
            *(__half2*)&oh[o1] = h1;
        }
    }
#undef LOAD_STAGE
}

// ---------------- fp16 GEMM (small-M): BM=64 BN=128 BK=32, 256 thr, 3 CTAs/SM --------
#define STG64_B  18432
#define GEMM64_SMEM 55296

template<int K>
__global__ __launch_bounds__(256, 3) void tgemm64_kernel(
    const fp16* __restrict__ A, const fp16* __restrict__ W,
    const float* __restrict__ bias,
    float* __restrict__ outf,
    fp16* __restrict__ oh,
    const float* __restrict__ resid,
    const float* __restrict__ ln_s, const float* __restrict__ ln_b) {
    extern __shared__ __align__(16) char sm[];
    uint32_t sb = smem_u32(sm);
    const int tid = threadIdx.x, lane = tid & 31, wid = tid >> 5;
    const int bm = blockIdx.y * 64;
    const int wm = (wid & 1) * 32, wn = (wid >> 1) * 32;
    constexpr int nst = K >> 5;

    const int asub = tid >> 7, at = tid & 127;
    const int arow = at >> 1, ahf = at & 1;
    const fp16* pa = A + (size_t)(bm + arow) * K + asub * 16 + ahf * 8;
    const uint32_t da = (uint32_t)(asub * 3072 + arow * 48 + ahf * 16);
    const int wrow = tid >> 1, whf = tid & 1;
    const fp16* pw = W + (size_t)wrow * K + whf * 8;
    const uint32_t dw = (uint32_t)(6144 + wrow * 48 + whf * 16);

    float acc[2][4][4];
#pragma unroll
    for (int i = 0; i < 2; i++)
#pragma unroll
        for (int j = 0; j < 4; j++)
#pragma unroll
            for (int c = 0; c < 4; c++) acc[i][j][c] = 0.f;

    const uint32_t aoff = (uint32_t)((lane & 15) * 48 + (lane >> 4) * 16);
    const uint32_t boff = (uint32_t)(((((lane >> 4) << 3) + (lane & 7)) * 48) + ((lane >> 3) & 1) * 16);

#define LOAD_STAGE64(s) do { \
    uint32_t base_ = sb + ((s) % 3) * STG64_B; \
    int ko_ = (s) * 32; \
    cp16(base_ + da,         pa + ko_); \
    cp16(base_ + dw,         pw + ko_); \
    cp16(base_ + 6144 + dw,  pw + ko_ + 16); \
} while (0)

    LOAD_STAGE64(0); CP_COMMIT();
    if (nst > 1) { LOAD_STAGE64(1); CP_COMMIT(); }

#pragma unroll 4
    for (int s = 0; s < nst; s++) {
        if (s + 1 < nst) CP_WAIT(1); else CP_WAIT(0);
        __syncthreads();
        if (s + 2 < nst) { LOAD_STAGE64(s + 2); CP_COMMIT(); }

        uint32_t base = sb + (s % 3) * STG64_B;
#pragma unroll
        for (int sub = 0; sub < 2; sub++) {
            uint32_t fa[2][4];
#pragma unroll
            for (int mi = 0; mi < 2; mi++)
                ldsm4(fa[mi], base + (uint32_t)sub * 3072u + (uint32_t)((wm + mi * 16) * 48) + aoff);
            uint32_t wb = base + 6144u + (uint32_t)sub * 6144u;
#pragma unroll
            for (int nj = 0; nj < 2; nj++) {
                uint32_t fw[4];
                ldsm4(fw, wb + (uint32_t)((wn + nj * 16) * 48) + boff);
#pragma unroll
                for (int mi = 0; mi < 2; mi++) {
                    mma_f16(acc[mi][nj * 2],     fa[mi], fw[0], fw[1]);
                    mma_f16(acc[mi][nj * 2 + 1], fa[mi], fw[2], fw[3]);
                }
            }
        }
    }
    __syncthreads();

    float* smf = (float*)sm;  // 64x128 f32 = 32KB
#pragma unroll
    for (int mi = 0; mi < 2; mi++) {
        int lr0 = wm + mi * 16 + (lane >> 2);
        int lr1 = lr0 + 8;
#pragma unroll
        for (int ni = 0; ni < 4; ni++) {
            int col = wn + ni * 8 + 2 * (lane & 3);
            float b0 = bias[col], b1 = bias[col + 1];
            size_t o0 = (size_t)(bm + lr0) * 128 + col, o1 = (size_t)(bm + lr1) * 128 + col;
            float v0 = acc[mi][ni][0] + b0 + resid[o0];
            float v1 = acc[mi][ni][1] + b1 + resid[o0 + 1];
            float v2 = acc[mi][ni][2] + b0 + resid[o1];
            float v3 = acc[mi][ni][3] + b1 + resid[o1 + 1];
            *(float2*)&outf[o0] = make_float2(v0, v1);
            *(float2*)&outf[o1] = make_float2(v2, v3);
            smf[lr0 * 128 + col] = v0; smf[lr0 * 128 + col + 1] = v1;
            smf[lr1 * 128 + col] = v2; smf[lr1 * 128 + col + 1] = v3;
        }
    }
    if (ln_s) {
        __syncthreads();
        float4 s4 = *(const float4*)(ln_s + lane * 4);
        float4 b4 = *(const float4*)(ln_b + lane * 4);
#pragma unroll
        for (int t = 0; t < 8; t++) {
            int rr = wid * 8 + t;
            float4 v = ((const float4*)smf)[rr * 32 + lane];
            float sum = (v.x + v.y) + (v.z + v.w);
            float sq  = fmaf(v.x, v.x, fmaf(v.y, v.y, fmaf(v.z, v.z, v.w * v.w)));
#pragma unroll
            for (int o = 16; o; o >>= 1) {
                sum += __shfl_xor_sync(0xffffffffu, sum, o);
                sq  += __shfl_xor_sync(0xffffffffu, sq, o);
            }
            float mu  = sum * (1.0f / 128.0f);
            float var = sq * (1.0f / 128.0f) - mu * mu;
            float inv = rsqrtf(var + 1e-5f);
            __half2 h0 = __floats2half2_rn((v.x - mu) * inv * s4.x + b4.x,
                                           (v.y - mu) * inv * s4.y + b4.y);
            __half2 h1 = __floats2half2_rn((v.z - mu) * inv * s4.z + b4.z,
                                           (v.w - mu) * inv * s4.w + b4.w);
            uint2 uh{*(uint32_t*)&h0, *(uint32_t*)&h1};
            *(uint2*)(oh + (size_t)(bm + rr) * 128 + lane * 4) = uh;
        }
    }
#undef LOAD_STAGE64
}

// ---------------- dense 12-node attention (round-13 version) ----------------
__global__ __launch_bounds__(64) void attn_kernel(const fp16* __restrict__ qkv,
                                                  const float* __restrict__ edge_bias,
                                                  fp16* __restrict__ mh) {
    __shared__ float sk[NODES * D];
    __shared__ float sv[NODES * D];
    __shared__ float seb[36];
    int b = blockIdx.x;
    const uint4* src = (const uint4*)(qkv + (size_t)b * NODES * 384);
    for (int i = threadIdx.x; i < NODES * 32; i += 64) {
        int node = i >> 5, c = i & 31;
        uint4 u = src[node * 48 + 16 + c];
        float* dp = (c < 16) ? &sk[node * D + c * 8] : &sv[node * D + (c - 16) * 8];
        float2 f0 = __half22float2(*(__half2*)&u.x);
        float2 f1 = __half22float2(*(__half2*)&u.y);
        float2 f2 = __half22float2(*(__half2*)&u.z);
        float2 f3 = __half22float2(*(__half2*)&u.w);
        dp[0] = f0.x; dp[1] = f0.y; dp[2] = f1.x; dp[3] = f1.y;
        dp[4] = f2.x; dp[5] = f2.y; dp[6] = f3.x; dp[7] = f3.y;
    }
    if (threadIdx.x < 36) seb[threadIdx.x] = edge_bias[threadIdx.x];
    __syncthreads();
    int tt = threadIdx.x;
    if (tt >= NODES * NHEAD) return;
    int dst = tt >> 2, hd = tt & 3;
    int kd = dst < 6 ? 0 : (dst < 11 ? 1 : 2);

    float q[DH];
    {
        const uint4* qp = src + dst * 48 + hd * 4;
#pragma unroll
        for (int i = 0; i < 4; i++) {
            uint4 u = qp[i];
            float2 f0 = __half22float2(*(__half2*)&u.x);
            float2 f1 = __half22float2(*(__half2*)&u.y);
            float2 f2 = __half22float2(*(__half2*)&u.z);
            float2 f3 = __half22float2(*(__half2*)&u.w);
            q[i * 8 + 0] = f0.x; q[i * 8 + 1] = f0.y; q[i * 8 + 2] = f1.x; q[i * 8 + 3] = f1.y;
            q[i * 8 + 4] = f2.x; q[i * 8 + 5] = f2.y; q[i * 8 + 6] = f3.x; q[i * 8 + 7] = f3.y;
        }
    }

    float logits[NODES];
    float mx = -1e30f;
#pragma unroll
    for (int j = 0; j < NODES; j++) {
        const float4* kp = (const float4*)&sk[j * D + hd * DH];
        float d0 = 0.f, d1 = 0.f, d2 = 0.f, d3 = 0.f;
#pragma unroll
        for (int i = 0; i < 8; i++) {
            float4 kv = kp[i];
            d0 = fmaf(q[i * 4 + 0], kv.x, d0);
            d1 = fmaf(q[i * 4 + 1], kv.y, d1);
            d2 = fmaf(q[i * 4 + 2], kv.z, d2);
            d3 = fmaf(q[i * 4 + 3], kv.w, d3);
        }
        int ks = j < 6 ? 0 : (j < 11 ? 1 : 2);
        float lg = ((d0 + d1) + (d2 + d3)) * SCALE + seb[(ks * 3 + kd) * NHEAD + hd];
        logits[j] = lg;
        mx = fmaxf(mx, lg);
    }
    float z = 0.f;
#pragma unroll
    for (int j = 0; j < NODES; j++) { logits[j] = __expf(logits[j] - mx); z += logits[j]; }
    float inv = 1.0f / z;

    float4 out[8];
#pragma unroll
    for (int i = 0; i < 8; i++) out[i] = make_float4(0.f, 0.f, 0.f, 0.f);
#pragma unroll
    for (int j = 0; j < NODES; j++) {
        float a = logits[j] * inv;
        const float4* vp = (const float4*)&sv[j * D + hd * DH];
#pragma unroll
        for (int i = 0; i < 8; i++) {
            float4 vv = vp[i];
            out[i].x = fmaf(a, vv.x, out[i].x);
            out[i].y = fmaf(a, vv.y, out[i].y);
            out[i].z = fmaf(a, vv.z, out[i].z);
            out[i].w = fmaf(a, vv.w, out[i].w);
        }
    }
    size_t ob = (size_t)b * NODES * D + dst * D + hd * DH;
#pragma unroll
    for (int i = 0; i < 8; i++) {
        __half2 h0 = __floats2half2_rn(out[i].x, out[i].y);
        __half2 h1 = __floats2half2_rn(out[i].z, out[i].w);
        uint2 uh{*(uint32_t*)&h0, *(uint32_t*)&h1};
        *(uint2*)(mh + ob + i * 4) = uh;
    }
}

// ---------------- final: gate/pool + proj + LN + gelu ----------------
__global__ void final_kernel(const float* __restrict__ x,
                             const float* __restrict__ gate_w, const float* __restrict__ gate_b,
                             const float* __restrict__ proj_w, const float* __restrict__ proj_b,
                             const float* __restrict__ pln_s, const float* __restrict__ pln_b,
                             float* __restrict__ out) {
    __shared__ float sx[NODES * D];
    __shared__ float sgate[NODES];
    __shared__ float comb[2 * D];
    __shared__ float red[4];
    int b = blockIdx.x, tid = threadIdx.x;
    for (int i = tid; i < NODES * D; i += 128) sx[i] = x[(size_t)b * NODES * D + i];
    __syncthreads();
    if (tid < NODES) {
        float acc = gate_b[0];
#pragma unroll 8
        for (int d = 0; d < D; d++) acc = fmaf(sx[tid * D + d], gate_w[d], acc);
        sgate[tid] = 1.0f / (1.0f + __expf(-acc));
    }
    __syncthreads();
    float pooled = 0.f;
#pragma unroll
    for (int n = 0; n < NODES; n++) pooled = fmaf(sx[n * D + tid], sgate[n], pooled);
    comb[tid]     = sx[11 * D + tid];
    comb[D + tid] = pooled;
    __syncthreads();
    float y = proj_b[tid];
#pragma unroll 8
    for (int c = 0; c < 2 * D; c++) y = fmaf(comb[c], proj_w[c * D + tid], y);
    float sum = y;
#pragma unroll
    for (int o = 16; o; o >>= 1) sum += __shfl_xor_sync(0xffffffffu, sum, o);
    if ((tid & 31) == 0) red[tid >> 5] = sum;
    __syncthreads();
    float mu = (red[0] + red[1] + red[2] + red[3]) * (1.0f / 128.0f);
    float c0 = y - mu;
    float cs = c0 * c0;
#pragma unroll
    for (int o = 16; o; o >>= 1) cs += __shfl_xor_sync(0xffffffffu, cs, o);
    __syncthreads();
    if ((tid & 31) == 0) red[tid >> 5] = cs;
    __syncthreads();
    float var = (red[0] + red[1] + red[2] + red[3]) * (1.0f / 128.0f);
    float yn = c0 * rsqrtf(var + 1e-5f) * pln_s[tid] + pln_b[tid];
    out[(size_t)b * D + tid] = gelu_exact(yn);
}

// ---------------- host orchestration ----------------
extern "C" void kernel_launch(void* const* d_in, const int* in_sizes, int n_in,
                              void* d_out, int out_size) {
    const float* patch   = (const float*)d_in[0];
    const float* band    = (const float*)d_in[1];
    const float* summ    = (const float*)d_in[2];
    const float* ln1_s   = (const float*)d_in[3];
    const float* ln1_b   = (const float*)d_in[4];
    const float* wq      = (const float*)d_in[5];
    const float* bq      = (const float*)d_in[6];
    const float* wk      = (const float*)d_in[7];
    const float* bk      = (const float*)d_in[8];
    const float* wv      = (const float*)d_in[9];
    const float* bv      = (const float*)d_in[10];
    const float* wo      = (const float*)d_in[11];
    const float* bo      = (const float*)d_in[12];
    const float* edge_b  = (const float*)d_in[13];
    const float* ln2_s   = (const float*)d_in[14];
    const float* ln2_b   = (const float*)d_in[15];
    const float* w1      = (const float*)d_in[16];
    const float* b1      = (const float*)d_in[17];
    const float* w2      = (const float*)d_in[18];
    const float* b2      = (const float*)d_in[19];
    const float* gate_w  = (const float*)d_in[20];
    const float* gate_b  = (const float*)d_in[21];
    const float* proj_w  = (const float*)d_in[22];
    const float* proj_b  = (const float*)d_in[23];
    const float* pln_s   = (const float*)d_in[24];
    const float* pln_b   = (const float*)d_in[25];
    float* out = (float*)d_out;

    float *x, *bqkv;
    fp16 *qkv, *hbuf, *mbuf, *tbuf;
    fp16 *wqkvw, *wow, *w1w, *w2w;
    cudaGetSymbolAddress((void**)&x,     g_x);
    cudaGetSymbolAddress((void**)&qkv,   g_qkv);
    cudaGetSymbolAddress((void**)&bqkv,  g_bqkv);
    cudaGetSymbolAddress((void**)&hbuf,  g_h);
    cudaGetSymbolAddress((void**)&mbuf,  g_m);
    cudaGetSymbolAddress((void**)&tbuf,  g_t);
    cudaGetSymbolAddress((void**)&wqkvw, g_wqkv);
    cudaGetSymbolAddress((void**)&wow,   g_wo);
    cudaGetSymbolAddress((void**)&w1w,   g_w1);
    cudaGetSymbolAddress((void**)&w2w,   g_w2);

    static int smem_set = 0;
    if (!smem_set) {
        cudaFuncSetAttribute(tgemm_kernel<128>, cudaFuncAttributeMaxDynamicSharedMemorySize, GEMM_SMEM);
        cudaFuncSetAttribute(tgemm64_kernel<128>, cudaFuncAttributeMaxDynamicSharedMemorySize, GEMM64_SMEM);
        cudaFuncSetAttribute(tgemm64_kernel<512>, cudaFuncAttributeMaxDynamicSharedMemorySize, GEMM64_SMEM);
        smem_set = 1;
    }

    init_ln_kernel<<<NTOK / 4, 128>>>(patch, band, summ, ln1_s, ln1_b, x, hbuf);
    pack_qkvw_kernel<<<(98304 + 255) / 256, 256>>>(wq, wk, wv, bq, bk, bv, wqkvw, bqkv);
    pack_rest_kernel<<<(294912 + 255) / 256, 256>>>(wo, w1, w2, wow, w1w, w2w);

    const int MT = NTOK / 128;    // 192
    const int MT64 = NTOK / 64;   // 384
    for (int l = 0; l < 2; l++) {
        tgemm_kernel<128><<<dim3(3, MT), 256, GEMM_SMEM>>>(
            hbuf, wqkvw + (size_t)l * 384 * 128, bqkv + l * 384, qkv, 384, 0);
        attn_kernel<<<BATCH, 64>>>(qkv, edge_b + l * 36, mbuf);
        tgemm64_kernel<128><<<dim3(1, MT64), 256, GEMM64_SMEM>>>(
            mbuf, wow + (size_t)l * 128 * 128,
            bo + l * 128, x, hbuf, x, ln2_s + l * 128, ln2_b + l * 128);
        tgemm_kernel<128><<<dim3(4, MT), 256, GEMM_SMEM>>>(
            hbuf, w1w + (size_t)l * 512 * 128, b1 + l * 512, tbuf, 512, 2);
        const float* nls = (l == 0) ? (ln1_s + 128) : nullptr;
        const float* nlb = (l == 0) ? (ln1_b + 128) : nullptr;
        tgemm64_kernel<512><<<dim3(1, MT64), 256, GEMM64_SMEM>>>(
            tbuf, w2w + (size_t)l * 128 * 512,
            b2 + l * 128, x, hbuf, x, nls, nlb);
    }

    final_kernel<<<BATCH, 128>>>(x, gate_w, gate_b, proj_w, proj_b, pln_s, pln_b, out);
}

// round 17
// speedup vs baseline: 1.0589x; 1.0184x over previous
#include <cuda_runtime.h>
#include <cuda_fp16.h>
#include <math.h>
#include <stdint.h>

#define BATCH      2048
#define NODES      12
#define NTOK       (BATCH * NODES)     // 24576
#define D          128
#define F          512
#define NHEAD      4
#define DH         32
#define SCALE      0.17677669529663687f

typedef __half fp16;

// ---------------- scratch (device globals; no allocation) ----------------
__device__ __align__(16) float g_x   [NTOK * D];
__device__ __align__(16) fp16 g_qkv [NTOK * 384];
__device__ __align__(16) fp16 g_h [NTOK * D];
__device__ __align__(16) fp16 g_m [NTOK * D];
__device__ __align__(16) fp16 g_t [NTOK * F];
__device__ __align__(16) fp16 g_wqkv[2 * 384 * D];   // [l][n][k]
__device__ __align__(16) fp16 g_wo  [2 * D * D];
__device__ __align__(16) fp16 g_w1  [2 * F * D];
__device__ __align__(16) fp16 g_w2  [2 * D * F];
__device__ float g_bqkv[2 * 384];

__device__ __forceinline__ float gelu_exact(float x) {
    return 0.5f * x * (1.0f + erff(x * 0.7071067811865476f));
}
__device__ __forceinline__ uint32_t smem_u32(const void* p) {
    uint32_t a;
    asm("{ .reg .u64 t; cvta.to.shared.u64 t, %1; cvt.u32.u64 %0, t; }" : "=r"(a) : "l"(p));
    return a;
}
__device__ __forceinline__ void cp16(uint32_t dst, const void* src) {
    asm volatile("cp.async.cg.shared.global [%0], [%1], 16;" :: "r"(dst), "l"(src));
}
#define CP_COMMIT() asm volatile("cp.async.commit_group;" ::: "memory")
#define CP_WAIT(n)  asm volatile("cp.async.wait_group %0;" :: "n"(n) : "memory")

__device__ __forceinline__ void ldsm4(uint32_t* r, uint32_t addr) {
    asm volatile("ldmatrix.sync.aligned.m8n8.x4.shared.b16 {%0,%1,%2,%3}, [%4];"
        : "=r"(r[0]), "=r"(r[1]), "=r"(r[2]), "=r"(r[3]) : "r"(addr));
}
__device__ __forceinline__ void mma_f16(float* c, const uint32_t* a, uint32_t b0, uint32_t b1) {
    asm volatile(
        "mma.sync.aligned.m16n8k16.row.col.f32.f16.f16.f32 "
        "{%0,%1,%2,%3}, {%4,%5,%6,%7}, {%8,%9}, {%0,%1,%2,%3};"
        : "+f"(c[0]), "+f"(c[1]), "+f"(c[2]), "+f"(c[3])
        : "r"(a[0]), "r"(a[1]), "r"(a[2]), "r"(a[3]), "r"(b0), "r"(b1));
}

// ---------------- fused setup: init+LN1(layer0) and all weight packing ----------------
// blocks [0,3072): init+LN (8 rows/block); [3072,3456): qkv weights; [3456,4608): rest
__global__ void setup_kernel(const float* __restrict__ patch,
                             const float* __restrict__ band,
                             const float* __restrict__ summ,
                             const float* __restrict__ s, const float* __restrict__ b,
                             float* __restrict__ x, fp16* __restrict__ oh,
                             const float* __restrict__ wq, const float* __restrict__ wk,
                             const float* __restrict__ wv,
                             const float* __restrict__ bq, const float* __restrict__ bk,
                             const float* __restrict__ bv,
                             fp16* __restrict__ qw, float* __restrict__ bqkv,
                             const float* __restrict__ wo,
                             const float* __restrict__ w1, const float* __restrict__ w2,
                             fp16* __restrict__ ow, fp16* __restrict__ w1w,
                             fp16* __restrict__ w2w) {
    int blk = blockIdx.x, tid = threadIdx.x;
    if (blk < 3072) {
        int row  = blk * 8 + (tid >> 5);
        int lane = tid & 31;
        int node = row % NODES;
        int bb   = row / NODES;
        float v[4];
        float sum = 0.f;
#pragma unroll
        for (int i = 0; i < 4; i++) {
            int d = lane + 32 * i;
            float val;
            if (node < 6)       val = patch[(size_t)(bb * 6 + node) * D + d];
            else if (node < 11) val = band [(size_t)(bb * 5 + (node - 6)) * D + d];
            else                val = summ[d];
            v[i] = val;
            x[(size_t)row * D + d] = val;
            sum += val;
        }
#pragma unroll
        for (int o = 16; o; o >>= 1) sum += __shfl_xor_sync(0xffffffffu, sum, o);
        float mu = sum * (1.0f / 128.0f);
        float sq = 0.f;
#pragma unroll
        for (int i = 0; i < 4; i++) { float c = v[i] - mu; sq += c * c; }
#pragma unroll
        for (int o = 16; o; o >>= 1) sq += __shfl_xor_sync(0xffffffffu, sq, o);
        float inv = rsqrtf(sq * (1.0f / 128.0f) + 1e-5f);
#pragma unroll
        for (int i = 0; i < 4; i++) {
            int d = lane + 32 * i;
            float y = (v[i] - mu) * inv * s[d] + b[d];
            oh[(size_t)row * D + d] = __float2half_rn(y);
        }
    } else if (blk < 3456) {
        int idx = (blk - 3072) * 256 + tid;   // < 98304
        {
            int l = idx / 49152, r = idx % 49152;
            int n = r / 128, k = r % 128;
            const float* src = (n < 128) ? wq : ((n < 256) ? wk : wv);
            qw[idx] = __float2half_rn(src[(size_t)l * 16384 + k * 128 + (n & 127)]);
        }
        if (idx < 768) {
            int l = idx / 384, n = idx % 384;
            const float* sb = (n < 128) ? bq : ((n < 256) ? bk : bv);
            bqkv[idx] = sb[l * 128 + (n & 127)];
        }
    } else {
        int idx = (blk - 3456) * 256 + tid;   // < 294912
        if (idx < 32768) {
            int l = idx / 16384, r = idx % 16384;
            int n = r / 128, k = r % 128;
            ow[idx] = __float2half_rn(wo[(size_t)l * 16384 + k * 128 + n]);
        } else if (idx < 163840) {
            int t = idx - 32768;
            int l = t / 65536, r = t % 65536;
            int n = r / 128, k = r % 128;
            w1w[t] = __float2half_rn(w1[(size_t)l * 65536 + (size_t)k * 512 + n]);
        } else {
            int t = idx - 163840;
            int l = t / 65536, r = t % 65536;
            int n = r / 512, k = r % 512;
            w2w[t] = __float2half_rn(w2[(size_t)l * 65536 + (size_t)k * 128 + n]);
        }
    }
}

// ---------------- fp16 GEMM (big): BM=128 BN=128 BK=32, 256 thr, 2 CTAs/SM ------------
// fw 1-deep software pipeline over flattened (sub,nj); K compile-time.
// mode 0: oh = half(D + bias);  mode 2: oh = half(gelu(D+bias))
#define STG_B   24576
#define GEMM_SMEM 73728

template<int K>
__global__ __launch_bounds__(256, 2) void tgemm_kernel(
    const fp16* __restrict__ A, const fp16* __restrict__ W,
    const float* __restrict__ bias,
    fp16* __restrict__ oh, int ldh, int mode) {
    extern __shared__ __align__(16) char sm[];
    uint32_t sb = smem_u32(sm);
    const int tid = threadIdx.x, lane = tid & 31, wid = tid >> 5;
    const int bm = blockIdx.y * 128, bn = blockIdx.x * 128;
    const int wm = (wid & 3) * 32, wn = (wid >> 2) * 64;
    constexpr int nst = K >> 5;

    const int lrow = tid >> 1, lhf = tid & 1;
    const fp16* p0 = A + (size_t)(bm + lrow) * K + lhf * 8;
    const fp16* p1 = W + (size_t)(bn + lrow) * K + lhf * 8;
    const uint32_t d0 = (uint32_t)(lrow * 48 + lhf * 16);

    float acc[2][8][4];
#pragma unroll
    for (int i = 0; i < 2; i++)
#pragma unroll
        for (int j = 0; j < 8; j++)
#pragma unroll
            for (int c = 0; c < 4; c++) acc[i][j][c] = 0.f;

    const uint32_t aoff = (uint32_t)((lane & 15) * 48 + (lane >> 4) * 16);
    const uint32_t boff = (uint32_t)(((((lane >> 4) << 3) + (lane & 7)) * 48) + ((lane >> 3) & 1) * 16);

#define LOAD_STAGE(s) do { \
    uint32_t base_ = sb + ((s) % 3) * STG_B; \
    int ko_ = (s) * 32; \
    cp16(base_ + d0,          p0 + ko_); \
    cp16(base_ + 6144 + d0,   p0 + ko_ + 16); \
    cp16(base_ + 12288 + d0,  p1 + ko_); \
    cp16(base_ + 18432 + d0,  p1 + ko_ + 16); \
} while (0)

    LOAD_STAGE(0); CP_COMMIT();
    if (nst > 1) { LOAD_STAGE(1); CP_COMMIT(); }

#pragma unroll
    for (int s = 0; s < nst; s++) {
        if (s + 1 < nst) CP_WAIT(1); else CP_WAIT(0);
        __syncthreads();
        if (s + 2 < nst) { LOAD_STAGE(s + 2); CP_COMMIT(); }

        uint32_t base = sb + (s % 3) * STG_B;
        uint32_t fa[2][2][4];
#pragma unroll
        for (int mi = 0; mi < 2; mi++) {
            uint32_t ad = base + (uint32_t)((wm + mi * 16) * 48) + aoff;
            ldsm4(fa[0][mi], ad);
            ldsm4(fa[1][mi], ad + 6144);
        }
        // flattened (sub,nj) with 1-deep fw pipeline
        auto waddr = [&](int j) {
            return base + 12288u + (uint32_t)((j >> 2) * 6144)
                 + (uint32_t)((wn + (j & 3) * 16) * 48) + boff;
        };
        uint32_t fwb[2][4];
        ldsm4(fwb[0], waddr(0));
#pragma unroll
        for (int j = 0; j < 8; j++) {
            if (j < 7) ldsm4(fwb[(j + 1) & 1], waddr(j + 1));
            const uint32_t* fw = fwb[j & 1];
            int sub = j >> 2, nj = j & 3;
#pragma unroll
            for (int mi = 0; mi < 2; mi++) {
                mma_f16(acc[mi][nj * 2],     fa[sub][mi], fw[0], fw[1]);
                mma_f16(acc[mi][nj * 2 + 1], fa[sub][mi], fw[2], fw[3]);
            }
        }
    }

#pragma unroll
    for (int mi = 0; mi < 2; mi++) {
        int r0 = bm + wm + mi * 16 + (lane >> 2);
        int r1 = r0 + 8;
#pragma unroll
        for (int ni = 0; ni < 8; ni++) {
            int col = bn + wn + ni * 8 + 2 * (lane & 3);
            float b0 = bias[col], b1 = bias[col + 1];
            float v0 = acc[mi][ni][0] + b0, v1 = acc[mi][ni][1] + b1;
            float v2 = acc[mi][ni][2] + b0, v3 = acc[mi][ni][3] + b1;
            size_t o0 = (size_t)r0 * ldh + col, o1 = (size_t)r1 * ldh + col;
            if (mode == 2) {
                v0 = gelu_exact(v0); v1 = gelu_exact(v1);
                v2 = gelu_exact(v2); v3 = gelu_exact(v3);
            }
            __half2 h0 = __floats2half2_rn(v0, v1);
            __half2 h1 = __floats2half2_rn(v2, v3);
            *(__half2*)&oh[o0] = h0;
            *(__half2*)&oh[o1] = h1;
        }
    }
#undef LOAD_STAGE
}

// ---------------- fp16 GEMM (small-M): BM=64 BN=128 BK=32, 256 thr, 3 CTAs/SM --------
#define STG64_B  18432
#define GEMM64_SMEM 55296

template<int K>
__global__ __launch_bounds__(256, 3) void tgemm64_kernel(
    const fp16* __restrict__ A, const fp16* __restrict__ W,
    const float* __restrict__ bias,
    float* __restrict__ outf,
    fp16* __restrict__ oh,
    const float* __restrict__ resid,
    const float* __restrict__ ln_s, const float* __restrict__ ln_b) {
    extern __shared__ __align__(16) char sm[];
    uint32_t sb = smem_u32(sm);
    const int tid = threadIdx.x, lane = tid & 31, wid = tid >> 5;
    const int bm = blockIdx.y * 64;
    const int wm = (wid & 1) * 32, wn = (wid >> 1) * 32;
    constexpr int nst = K >> 5;

    const int asub = tid >> 7, at = tid & 127;
    const int arow = at >> 1, ahf = at & 1;
    const fp16* pa = A + (size_t)(bm + arow) * K + asub * 16 + ahf * 8;
    const uint32_t da = (uint32_t)(asub * 3072 + arow * 48 + ahf * 16);
    const int wrow = tid >> 1, whf = tid & 1;
    const fp16* pw = W + (size_t)wrow * K + whf * 8;
    const uint32_t dw = (uint32_t)(6144 + wrow * 48 + whf * 16);

    float acc[2][4][4];
#pragma unroll
    for (int i = 0; i < 2; i++)
#pragma unroll
        for (int j = 0; j < 4; j++)
#pragma unroll
            for (int c = 0; c < 4; c++) acc[i][j][c] = 0.f;

    const uint32_t aoff = (uint32_t)((lane & 15) * 48 + (lane >> 4) * 16);
    const uint32_t boff = (uint32_t)(((((lane >> 4) << 3) + (lane & 7)) * 48) + ((lane >> 3) & 1) * 16);

#define LOAD_STAGE64(s) do { \
    uint32_t base_ = sb + ((s) % 3) * STG64_B; \
    int ko_ = (s) * 32; \
    cp16(base_ + da,         pa + ko_); \
    cp16(base_ + dw,         pw + ko_); \
    cp16(base_ + 6144 + dw,  pw + ko_ + 16); \
} while (0)

    LOAD_STAGE64(0); CP_COMMIT();
    if (nst > 1) { LOAD_STAGE64(1); CP_COMMIT(); }

#pragma unroll 4
    for (int s = 0; s < nst; s++) {
        if (s + 1 < nst) CP_WAIT(1); else CP_WAIT(0);
        __syncthreads();
        if (s + 2 < nst) { LOAD_STAGE64(s + 2); CP_COMMIT(); }

        uint32_t base = sb + (s % 3) * STG64_B;
#pragma unroll
        for (int sub = 0; sub < 2; sub++) {
            uint32_t fa[2][4];
#pragma unroll
            for (int mi = 0; mi < 2; mi++)
                ldsm4(fa[mi], base + (uint32_t)sub * 3072u + (uint32_t)((wm + mi * 16) * 48) + aoff);
            uint32_t wb = base + 6144u + (uint32_t)sub * 6144u;
#pragma unroll
            for (int nj = 0; nj < 2; nj++) {
                uint32_t fw[4];
                ldsm4(fw, wb + (uint32_t)((wn + nj * 16) * 48) + boff);
#pragma unroll
                for (int mi = 0; mi < 2; mi++) {
                    mma_f16(acc[mi][nj * 2],     fa[mi], fw[0], fw[1]);
                    mma_f16(acc[mi][nj * 2 + 1], fa[mi], fw[2], fw[3]);
                }
            }
        }
    }
    __syncthreads();

    float* smf = (float*)sm;  // 64x128 f32 = 32KB
#pragma unroll
    for (int mi = 0; mi < 2; mi++) {
        int lr0 = wm + mi * 16 + (lane >> 2);
        int lr1 = lr0 + 8;
#pragma unroll
        for (int ni = 0; ni < 4; ni++) {
            int col = wn + ni * 8 + 2 * (lane & 3);
            float b0 = bias[col], b1 = bias[col + 1];
            size_t o0 = (size_t)(bm + lr0) * 128 + col, o1 = (size_t)(bm + lr1) * 128 + col;
            float v0 = acc[mi][ni][0] + b0 + resid[o0];
            float v1 = acc[mi][ni][1] + b1 + resid[o0 + 1];
            float v2 = acc[mi][ni][2] + b0 + resid[o1];
            float v3 = acc[mi][ni][3] + b1 + resid[o1 + 1];
            *(float2*)&outf[o0] = make_float2(v0, v1);
            *(float2*)&outf[o1] = make_float2(v2, v3);
            smf[lr0 * 128 + col] = v0; smf[lr0 * 128 + col + 1] = v1;
            smf[lr1 * 128 + col] = v2; smf[lr1 * 128 + col + 1] = v3;
        }
    }
    if (ln_s) {
        __syncthreads();
        float4 s4 = *(const float4*)(ln_s + lane * 4);
        float4 b4 = *(const float4*)(ln_b + lane * 4);
#pragma unroll
        for (int t = 0; t < 8; t++) {
            int rr = wid * 8 + t;
            float4 v = ((const float4*)smf)[rr * 32 + lane];
            float sum = (v.x + v.y) + (v.z + v.w);
            float sq  = fmaf(v.x, v.x, fmaf(v.y, v.y, fmaf(v.z, v.z, v.w * v.w)));
#pragma unroll
            for (int o = 16; o; o >>= 1) {
                sum += __shfl_xor_sync(0xffffffffu, sum, o);
                sq  += __shfl_xor_sync(0xffffffffu, sq, o);
            }
            float mu  = sum * (1.0f / 128.0f);
            float var = sq * (1.0f / 128.0f) - mu * mu;
            float inv = rsqrtf(var + 1e-5f);
            __half2 h0 = __floats2half2_rn((v.x - mu) * inv * s4.x + b4.x,
                                           (v.y - mu) * inv * s4.y + b4.y);
            __half2 h1 = __floats2half2_rn((v.z - mu) * inv * s4.z + b4.z,
                                           (v.w - mu) * inv * s4.w + b4.w);
            uint2 uh{*(uint32_t*)&h0, *(uint32_t*)&h1};
            *(uint2*)(oh + (size_t)(bm + rr) * 128 + lane * 4) = uh;
        }
    }
#undef LOAD_STAGE64
}

// ---------------- dense 12-node attention ----------------
__global__ __launch_bounds__(64) void attn_kernel(const fp16* __restrict__ qkv,
                                                  const float* __restrict__ edge_bias,
                                                  fp16* __restrict__ mh) {
    __shared__ float sk[NODES * D];
    __shared__ float sv[NODES * D];
    __shared__ float seb[36];
    int b = blockIdx.x;
    const uint4* src = (const uint4*)(qkv + (size_t)b * NODES * 384);
    for (int i = threadIdx.x; i < NODES * 32; i += 64) {
        int node = i >> 5, c = i & 31;
        uint4 u = src[node * 48 + 16 + c];
        float* dp = (c < 16) ? &sk[node * D + c * 8] : &sv[node * D + (c - 16) * 8];
        float2 f0 = __half22float2(*(__half2*)&u.x);
        float2 f1 = __half22float2(*(__half2*)&u.y);
        float2 f2 = __half22float2(*(__half2*)&u.z);
        float2 f3 = __half22float2(*(__half2*)&u.w);
        dp[0] = f0.x; dp[1] = f0.y; dp[2] = f1.x; dp[3] = f1.y;
        dp[4] = f2.x; dp[5] = f2.y; dp[6] = f3.x; dp[7] = f3.y;
    }
    if (threadIdx.x < 36) seb[threadIdx.x] = edge_bias[threadIdx.x];
    __syncthreads();
    int tt = threadIdx.x;
    if (tt >= NODES * NHEAD) return;
    int dst = tt >> 2, hd = tt & 3;
    int kd = dst < 6 ? 0 : (dst < 11 ? 1 : 2);

    float q[DH];
    {
        const uint4* qp = src + dst * 48 + hd * 4;
#pragma unroll
        for (int i = 0; i < 4; i++) {
            uint4 u = qp[i];
            float2 f0 = __half22float2(*(__half2*)&u.x);
            float2 f1 = __half22float2(*(__half2*)&u.y);
            float2 f2 = __half22float2(*(__half2*)&u.z);
            float2 f3 = __half22float2(*(__half2*)&u.w);
            q[i * 8 + 0] = f0.x; q[i * 8 + 1] = f0.y; q[i * 8 + 2] = f1.x; q[i * 8 + 3] = f1.y;
            q[i * 8 + 4] = f2.x; q[i * 8 + 5] = f2.y; q[i * 8 + 6] = f3.x; q[i * 8 + 7] = f3.y;
        }
    }

    float logits[NODES];
    float mx = -1e30f;
#pragma unroll
    for (int j = 0; j < NODES; j++) {
        const float4* kp = (const float4*)&sk[j * D + hd * DH];
        float d0 = 0.f, d1 = 0.f, d2 = 0.f, d3 = 0.f;
#pragma unroll
        for (int i = 0; i < 8; i++) {
            float4 kv = kp[i];
            d0 = fmaf(q[i * 4 + 0], kv.x, d0);
            d1 = fmaf(q[i * 4 + 1], kv.y, d1);
            d2 = fmaf(q[i * 4 + 2], kv.z, d2);
            d3 = fmaf(q[i * 4 + 3], kv.w, d3);
        }
        int ks = j < 6 ? 0 : (j < 11 ? 1 : 2);
        float lg = ((d0 + d1) + (d2 + d3)) * SCALE + seb[(ks * 3 + kd) * NHEAD + hd];
        logits[j] = lg;
        mx = fmaxf(mx, lg);
    }
    float z = 0.f;
#pragma unroll
    for (int j = 0; j < NODES; j++) { logits[j] = __expf(logits[j] - mx); z += logits[j]; }
    float inv = 1.0f / z;

    float4 out[8];
#pragma unroll
    for (int i = 0; i < 8; i++) out[i] = make_float4(0.f, 0.f, 0.f, 0.f);
#pragma unroll
    for (int j = 0; j < NODES; j++) {
        float a = logits[j] * inv;
        const float4* vp = (const float4*)&sv[j * D + hd * DH];
#pragma unroll
        for (int i = 0; i < 8; i++) {
            float4 vv = vp[i];
            out[i].x = fmaf(a, vv.x, out[i].x);
            out[i].y = fmaf(a, vv.y, out[i].y);
            out[i].z = fmaf(a, vv.z, out[i].z);
            out[i].w = fmaf(a, vv.w, out[i].w);
        }
    }
    size_t ob = (size_t)b * NODES * D + dst * D + hd * DH;
#pragma unroll
    for (int i = 0; i < 8; i++) {
        __half2 h0 = __floats2half2_rn(out[i].x, out[i].y);
        __half2 h1 = __floats2half2_rn(out[i].z, out[i].w);
        uint2 uh{*(uint32_t*)&h0, *(uint32_t*)&h1};
        *(uint2*)(mh + ob + i * 4) = uh;
    }
}

// ---------------- final: gate/pool + proj + LN + gelu ----------------
__global__ void final_kernel(const float* __restrict__ x,
                             const float* __restrict__ gate_w, const float* __restrict__ gate_b,
                             const float* __restrict__ proj_w, const float* __restrict__ proj_b,
                             const float* __restrict__ pln_s, const float* __restrict__ pln_b,
                             float* __restrict__ out) {
    __shared__ float sx[NODES * D];
    __shared__ float sgate[NODES];
    __shared__ float comb[2 * D];
    __shared__ float red[4];
    int b = blockIdx.x, tid = threadIdx.x;
    for (int i = tid; i < NODES * D; i += 128) sx[i] = x[(size_t)b * NODES * D + i];
    __syncthreads();
    if (tid < NODES) {
        float acc = gate_b[0];
#pragma unroll 8
        for (int d = 0; d < D; d++) acc = fmaf(sx[tid * D + d], gate_w[d], acc);
        sgate[tid] = 1.0f / (1.0f + __expf(-acc));
    }
    __syncthreads();
    float pooled = 0.f;
#pragma unroll
    for (int n = 0; n < NODES; n++) pooled = fmaf(sx[n * D + tid], sgate[n], pooled);
    comb[tid]     = sx[11 * D + tid];
    comb[D + tid] = pooled;
    __syncthreads();
    float y = proj_b[tid];
#pragma unroll 8
    for (int c = 0; c < 2 * D; c++) y = fmaf(comb[c], proj_w[c * D + tid], y);
    float sum = y;
#pragma unroll
    for (int o = 16; o; o >>= 1) sum += __shfl_xor_sync(0xffffffffu, sum, o);
    if ((tid & 31) == 0) red[tid >> 5] = sum;
    __syncthreads();
    float mu = (red[0] + red[1] + red[2] + red[3]) * (1.0f / 128.0f);
    float c0 = y - mu;
    float cs = c0 * c0;
#pragma unroll
    for (int o = 16; o; o >>= 1) cs += __shfl_xor_sync(0xffffffffu, cs, o);
    __syncthreads();
    if ((tid & 31) == 0) red[tid >> 5] = cs;
    __syncthreads();
    float var = (red[0] + red[1] + red[2] + red[3]) * (1.0f / 128.0f);
    float yn = c0 * rsqrtf(var + 1e-5f) * pln_s[tid] + pln_b[tid];
    out[(size_t)b * D + tid] = gelu_exact(yn);
}

// ---------------- host orchestration ----------------
extern "C" void kernel_launch(void* const* d_in, const int* in_sizes, int n_in,
                              void* d_out, int out_size) {
    const float* patch   = (const float*)d_in[0];
    const float* band    = (const float*)d_in[1];
    const float* summ    = (const float*)d_in[2];
    const float* ln1_s   = (const float*)d_in[3];
    const float* ln1_b   = (const float*)d_in[4];
    const float* wq      = (const float*)d_in[5];
    const float* bq      = (const float*)d_in[6];
    const float* wk      = (const float*)d_in[7];
    const float* bk      = (const float*)d_in[8];
    const float* wv      = (const float*)d_in[9];
    const float* bv      = (const float*)d_in[10];
    const float* wo      = (const float*)d_in[11];
    const float* bo      = (const float*)d_in[12];
    const float* edge_b  = (const float*)d_in[13];
    const float* ln2_s   = (const float*)d_in[14];
    const float* ln2_b   = (const float*)d_in[15];
    const float* w1      = (const float*)d_in[16];
    const float* b1      = (const float*)d_in[17];
    const float* w2      = (const float*)d_in[18];
    const float* b2      = (const float*)d_in[19];
    const float* gate_w  = (const float*)d_in[20];
    const float* gate_b  = (const float*)d_in[21];
    const float* proj_w  = (const float*)d_in[22];
    const float* proj_b  = (const float*)d_in[23];
    const float* pln_s   = (const float*)d_in[24];
    const float* pln_b   = (const float*)d_in[25];
    float* out = (float*)d_out;

    float *x, *bqkv;
    fp16 *qkv, *hbuf, *mbuf, *tbuf;
    fp16 *wqkvw, *wow, *w1w, *w2w;
    cudaGetSymbolAddress((void**)&x,     g_x);
    cudaGetSymbolAddress((void**)&qkv,   g_qkv);
    cudaGetSymbolAddress((void**)&bqkv,  g_bqkv);
    cudaGetSymbolAddress((void**)&hbuf,  g_h);
    cudaGetSymbolAddress((void**)&mbuf,  g_m);
    cudaGetSymbolAddress((void**)&tbuf,  g_t);
    cudaGetSymbolAddress((void**)&wqkvw, g_wqkv);
    cudaGetSymbolAddress((void**)&wow,   g_wo);
    cudaGetSymbolAddress((void**)&w1w,   g_w1);
    cudaGetSymbolAddress((void**)&w2w,   g_w2);

    static int smem_set = 0;
    if (!smem_set) {
        cudaFuncSetAttribute(tgemm_kernel<128>, cudaFuncAttributeMaxDynamicSharedMemorySize, GEMM_SMEM);
        cudaFuncSetAttribute(tgemm64_kernel<128>, cudaFuncAttributeMaxDynamicSharedMemorySize, GEMM64_SMEM);
        cudaFuncSetAttribute(tgemm64_kernel<512>, cudaFuncAttributeMaxDynamicSharedMemorySize, GEMM64_SMEM);
        smem_set = 1;
    }

    setup_kernel<<<4608, 256>>>(patch, band, summ, ln1_s, ln1_b, x, hbuf,
                                wq, wk, wv, bq, bk, bv, wqkvw, bqkv,
                                wo, w1, w2, wow, w1w, w2w);

    const int MT = NTOK / 128;    // 192
    const int MT64 = NTOK / 64;   // 384
    for (int l = 0; l < 2; l++) {
        tgemm_kernel<128><<<dim3(3, MT), 256, GEMM_SMEM>>>(
            hbuf, wqkvw + (size_t)l * 384 * 128, bqkv + l * 384, qkv, 384, 0);
        attn_kernel<<<BATCH, 64>>>(qkv, edge_b + l * 36, mbuf);
        tgemm64_kernel<128><<<dim3(1, MT64), 256, GEMM64_SMEM>>>(
            mbuf, wow + (size_t)l * 128 * 128,
            bo + l * 128, x, hbuf, x, ln2_s + l * 128, ln2_b + l * 128);
        tgemm_kernel<128><<<dim3(4, MT), 256, GEMM_SMEM>>>(
            hbuf, w1w + (size_t)l * 512 * 128, b1 + l * 512, tbuf, 512, 2);
        const float* nls = (l == 0) ? (ln1_s + 128) : nullptr;
        const float* nlb = (l == 0) ? (ln1_b + 128) : nullptr;
        tgemm64_kernel<512><<<dim3(1, MT64), 256, GEMM64_SMEM>>>(
            tbuf, w2w + (size_t)l * 128 * 512,
            b2 + l * 128, x, hbuf, x, nls, nlb);
    }

    final_kernel<<<BATCH, 128>>>(x, gate_w, gate_b, proj_w, proj_b, pln_s, pln_b, out);
}